// round 2
// baseline (speedup 1.0000x reference)
#include <cuda_runtime.h>
#include <cstdint>

#define Bn 2
#define Sn 2048
#define Dn 1024
#define Hn 16
#define HDn 64
#define BHn (Bn*Hn)
#define Mn (Bn*Sn)       // 4096
#define KSEL 1024        // top-k count

// ---- scratch (static device allocations; no cudaMalloc allowed) ----
__device__ float g_Q[Bn*Hn*Sn*HDn];   // (b,h,s,hd)
__device__ float g_K[Bn*Hn*Sn*HDn];
__device__ float g_V[Bn*Hn*Sn*HDn];
__device__ float g_AV[Bn*Hn*Sn*HDn];

// ============================================================
// Kernel 1: projection  C = A @ W^T + bias, scatter to (b,h,s,hd)
// A: (M=4096, K=1024) row-major; W: (N=1024, K=1024) row-major
// ============================================================
__global__ __launch_bounds__(256) void proj_kernel(
    const float* __restrict__ A, const float* __restrict__ W,
    const float* __restrict__ bias, float* __restrict__ Out)
{
    const int BK = 16;
    __shared__ float As[BK][128];
    __shared__ float Bs[BK][128];
    int m0 = blockIdx.y * 128;
    int n0 = blockIdx.x * 128;
    int tid = threadIdx.x;
    float acc[8][8];
    #pragma unroll
    for (int i=0;i<8;i++)
        #pragma unroll
        for (int j=0;j<8;j++) acc[i][j]=0.f;

    for (int k0 = 0; k0 < Dn; k0 += BK) {
        #pragma unroll
        for (int i = 0; i < 2; i++) {
            int idx = tid + i*256;       // 0..511 float4 slots
            int r = idx >> 2;            // row in tile
            int c4 = idx & 3;
            float4 v = *(const float4*)(A + (size_t)(m0 + r)*Dn + k0 + c4*4);
            As[c4*4+0][r]=v.x; As[c4*4+1][r]=v.y; As[c4*4+2][r]=v.z; As[c4*4+3][r]=v.w;
        }
        #pragma unroll
        for (int i = 0; i < 2; i++) {
            int idx = tid + i*256;
            int r = idx >> 2;
            int c4 = idx & 3;
            float4 v = *(const float4*)(W + (size_t)(n0 + r)*Dn + k0 + c4*4);
            Bs[c4*4+0][r]=v.x; Bs[c4*4+1][r]=v.y; Bs[c4*4+2][r]=v.z; Bs[c4*4+3][r]=v.w;
        }
        __syncthreads();
        int tx = tid & 15, ty = tid >> 4;
        #pragma unroll
        for (int kk = 0; kk < BK; kk++) {
            float a[8], b[8];
            #pragma unroll
            for (int i=0;i<8;i++) a[i] = As[kk][ty*8+i];
            #pragma unroll
            for (int j=0;j<8;j++) b[j] = Bs[kk][tx*8+j];
            #pragma unroll
            for (int i=0;i<8;i++)
                #pragma unroll
                for (int j=0;j<8;j++) acc[i][j] += a[i]*b[j];
        }
        __syncthreads();
    }
    int tx = tid & 15, ty = tid >> 4;
    #pragma unroll
    for (int i=0;i<8;i++){
        int m = m0 + ty*8 + i;
        int b = m / Sn, s = m % Sn;
        #pragma unroll
        for (int j=0;j<8;j++){
            int n = n0 + tx*8 + j;
            int h = n >> 6, hd = n & 63;
            Out[(((size_t)(b*Hn + h))*Sn + s)*HDn + hd] = acc[i][j] + bias[n];
        }
    }
}

// ============================================================
// Kernel 2: scores[bh][q][k] = scale * dot(Q[bh][q], K[bh][k])
// ============================================================
__global__ __launch_bounds__(256) void scores_kernel(float* __restrict__ attn)
{
    const int BK = 16;
    __shared__ float As[BK][128];
    __shared__ float Bs[BK][128];
    int bh = blockIdx.z;
    int q0 = blockIdx.y * 128;
    int n0 = blockIdx.x * 128;
    const float* Qb = g_Q + (size_t)bh * Sn * HDn;
    const float* Kb = g_K + (size_t)bh * Sn * HDn;
    float* Cb = attn + (size_t)bh * Sn * Sn;
    int tid = threadIdx.x;
    float acc[8][8];
    #pragma unroll
    for (int i=0;i<8;i++)
        #pragma unroll
        for (int j=0;j<8;j++) acc[i][j]=0.f;

    for (int k0 = 0; k0 < HDn; k0 += BK) {
        #pragma unroll
        for (int i = 0; i < 2; i++) {
            int idx = tid + i*256;
            int r = idx >> 2;
            int c4 = idx & 3;
            float4 v = *(const float4*)(Qb + (size_t)(q0 + r)*HDn + k0 + c4*4);
            As[c4*4+0][r]=v.x; As[c4*4+1][r]=v.y; As[c4*4+2][r]=v.z; As[c4*4+3][r]=v.w;
        }
        #pragma unroll
        for (int i = 0; i < 2; i++) {
            int idx = tid + i*256;
            int r = idx >> 2;
            int c4 = idx & 3;
            float4 v = *(const float4*)(Kb + (size_t)(n0 + r)*HDn + k0 + c4*4);
            Bs[c4*4+0][r]=v.x; Bs[c4*4+1][r]=v.y; Bs[c4*4+2][r]=v.z; Bs[c4*4+3][r]=v.w;
        }
        __syncthreads();
        int tx = tid & 15, ty = tid >> 4;
        #pragma unroll
        for (int kk = 0; kk < BK; kk++) {
            float a[8], b[8];
            #pragma unroll
            for (int i=0;i<8;i++) a[i] = As[kk][ty*8+i];
            #pragma unroll
            for (int j=0;j<8;j++) b[j] = Bs[kk][tx*8+j];
            #pragma unroll
            for (int i=0;i<8;i++)
                #pragma unroll
                for (int j=0;j<8;j++) acc[i][j] += a[i]*b[j];
        }
        __syncthreads();
    }
    const float scale = 0.125f;   // HD^-0.5
    int tx = tid & 15, ty = tid >> 4;
    #pragma unroll
    for (int i=0;i<8;i++){
        int q = q0 + ty*8 + i;
        float* rowp = Cb + (size_t)q * Sn + n0 + tx*8;
        float4 v0 = make_float4(acc[i][0]*scale, acc[i][1]*scale, acc[i][2]*scale, acc[i][3]*scale);
        float4 v1 = make_float4(acc[i][4]*scale, acc[i][5]*scale, acc[i][6]*scale, acc[i][7]*scale);
        *(float4*)(rowp)     = v0;
        *(float4*)(rowp + 4) = v1;
    }
}

// ============================================================
// Kernel 3: per-row exact top-k threshold (race-free bitwise binary
// search on order-preserving uint keys) + masked softmax, in place.
// One block per (bh,q) row; 256 threads; row length 2048.
// All per-pass state (prefix, decision) is register-uniform: every
// thread derives it from the same shared reduction result, so there
// is no read/write race on shared scalars.
// ============================================================
__global__ __launch_bounds__(256) void topk_softmax_kernel(float* __restrict__ attn)
{
    __shared__ float redf[8];
    __shared__ int   redi[8];

    size_t row = blockIdx.x;
    float* rowp = attn + row * (size_t)Sn;
    int tid  = threadIdx.x;
    int lane = tid & 31;
    int wid  = tid >> 5;

    float x[8];
    unsigned uu[8];
    float lmax = __int_as_float(0xff800000);   // -inf
    #pragma unroll
    for (int i=0;i<8;i++){
        x[i] = rowp[tid + 256*i];
        lmax = fmaxf(lmax, x[i]);
        unsigned u = __float_as_uint(x[i]);
        uu[i] = (u & 0x80000000u) ? ~u : (u | 0x80000000u);   // order-preserving map
    }

    // global max (for softmax stability)
    #pragma unroll
    for (int o=16;o>0;o>>=1) lmax = fmaxf(lmax, __shfl_xor_sync(0xffffffffu, lmax, o));
    if (lane == 0) redf[wid] = lmax;
    __syncthreads();
    float gmax = redf[0];
    #pragma unroll
    for (int w=1;w<8;w++) gmax = fmaxf(gmax, redf[w]);

    // bitwise binary search for the k-th largest key:
    // prefix ends as max t with count(keys >= t) >= KSEL, i.e. the exact
    // k-th largest key (counting duplicates).
    unsigned prefix = 0u;
    #pragma unroll 1
    for (int bit = 31; bit >= 0; bit--) {
        unsigned t = prefix | (1u << bit);
        int c = 0;
        #pragma unroll
        for (int i=0;i<8;i++) c += (uu[i] >= t) ? 1 : 0;
        #pragma unroll
        for (int o=16;o>0;o>>=1) c += __shfl_xor_sync(0xffffffffu, c, o);
        __syncthreads();               // all reads of redi from prev iter done
        if (lane == 0) redi[wid] = c;
        __syncthreads();
        int total = 0;
        #pragma unroll
        for (int w=0;w<8;w++) total += redi[w];
        if (total >= KSEL) prefix = t; // uniform across all threads
    }
    unsigned thr = prefix;

    // masked softmax
    float ex[8];
    float lsum = 0.f;
    #pragma unroll
    for (int i=0;i<8;i++){
        ex[i] = (uu[i] >= thr) ? __expf(x[i] - gmax) : 0.f;
        lsum += ex[i];
    }
    #pragma unroll
    for (int o=16;o>0;o>>=1) lsum += __shfl_xor_sync(0xffffffffu, lsum, o);
    __syncthreads();                   // redi reads above are long done; reuse redf
    if (lane == 0) redf[wid] = lsum;
    __syncthreads();
    float tot = 0.f;
    #pragma unroll
    for (int w=0;w<8;w++) tot += redf[w];
    float inv = 1.f / tot;
    #pragma unroll
    for (int i=0;i<8;i++) rowp[tid + 256*i] = ex[i] * inv;
}

// ============================================================
// Kernel 4: AV[bh][q][d] = sum_k attn[bh][q][k] * V[bh][k][d]
// ============================================================
__global__ __launch_bounds__(256) void av_kernel(const float* __restrict__ attn)
{
    const int BK = 32;
    __shared__ float As[BK][128];   // [k][m]
    __shared__ float Bs[BK][64];    // [k][n]
    int bh = blockIdx.z;
    int m0 = blockIdx.y * 128;
    const float* Arow = attn + (size_t)bh * Sn * Sn;
    const float* Vb   = g_V  + (size_t)bh * Sn * HDn;
    float*       Cb   = g_AV + (size_t)bh * Sn * HDn;
    int tid = threadIdx.x;
    float acc[8][4];
    #pragma unroll
    for (int i=0;i<8;i++)
        #pragma unroll
        for (int j=0;j<4;j++) acc[i][j]=0.f;

    for (int k0 = 0; k0 < Sn; k0 += BK) {
        #pragma unroll
        for (int i = 0; i < 4; i++) {
            int idx = tid + i*256;     // 0..1023 float4 slots (128x32)
            int r = idx >> 3;          // 0..127
            int c4 = idx & 7;          // 0..7
            float4 v = *(const float4*)(Arow + (size_t)(m0 + r)*Sn + k0 + c4*4);
            As[c4*4+0][r]=v.x; As[c4*4+1][r]=v.y; As[c4*4+2][r]=v.z; As[c4*4+3][r]=v.w;
        }
        #pragma unroll
        for (int i = 0; i < 2; i++) {
            int idx = tid + i*256;     // 0..511 float4 slots (32x64)
            int r = idx >> 4;          // 0..31
            int c4 = idx & 15;         // 0..15
            float4 v = *(const float4*)(Vb + (size_t)(k0 + r)*HDn + c4*4);
            *(float4*)&Bs[r][c4*4] = v;
        }
        __syncthreads();
        int tx = tid & 15, ty = tid >> 4;
        #pragma unroll
        for (int kk = 0; kk < BK; kk++) {
            float a[8], b[4];
            #pragma unroll
            for (int i=0;i<8;i++) a[i] = As[kk][ty*8+i];
            #pragma unroll
            for (int j=0;j<4;j++) b[j] = Bs[kk][tx*4+j];
            #pragma unroll
            for (int i=0;i<8;i++)
                #pragma unroll
                for (int j=0;j<4;j++) acc[i][j] += a[i]*b[j];
        }
        __syncthreads();
    }
    int tx = tid & 15, ty = tid >> 4;
    #pragma unroll
    for (int i=0;i<8;i++){
        int m = m0 + ty*8 + i;
        float4 v = make_float4(acc[i][0], acc[i][1], acc[i][2], acc[i][3]);
        *(float4*)&Cb[(size_t)m*HDn + tx*4] = v;
    }
}

// ============================================================
// Kernel 5: out[m][n] = sum_k AVview[m][k] * Wo[n][k] + bo[n]
// AVview[m][k] = g_AV[((b*H + k/64)*S + s)*64 + k%64],  m = b*S+s
// ============================================================
__global__ __launch_bounds__(256) void outproj_kernel(
    const float* __restrict__ Wo, const float* __restrict__ bo,
    float* __restrict__ out)
{
    const int BK = 16;
    __shared__ float As[BK][128];
    __shared__ float Bs[BK][128];
    int m0 = blockIdx.y * 128;
    int n0 = blockIdx.x * 128;
    int tid = threadIdx.x;
    float acc[8][8];
    #pragma unroll
    for (int i=0;i<8;i++)
        #pragma unroll
        for (int j=0;j<8;j++) acc[i][j]=0.f;

    for (int k0 = 0; k0 < Dn; k0 += BK) {
        int h   = k0 >> 6;          // constant across the BK=16 tile
        int hd0 = k0 & 63;
        #pragma unroll
        for (int i = 0; i < 2; i++) {
            int idx = tid + i*256;
            int r = idx >> 2;
            int c4 = idx & 3;
            int m = m0 + r;
            int b = m / Sn, s = m % Sn;
            float4 v = *(const float4*)(g_AV + (((size_t)(b*Hn + h))*Sn + s)*HDn + hd0 + c4*4);
            As[c4*4+0][r]=v.x; As[c4*4+1][r]=v.y; As[c4*4+2][r]=v.z; As[c4*4+3][r]=v.w;
        }
        #pragma unroll
        for (int i = 0; i < 2; i++) {
            int idx = tid + i*256;
            int r = idx >> 2;
            int c4 = idx & 3;
            float4 v = *(const float4*)(Wo + (size_t)(n0 + r)*Dn + k0 + c4*4);
            Bs[c4*4+0][r]=v.x; Bs[c4*4+1][r]=v.y; Bs[c4*4+2][r]=v.z; Bs[c4*4+3][r]=v.w;
        }
        __syncthreads();
        int tx = tid & 15, ty = tid >> 4;
        #pragma unroll
        for (int kk = 0; kk < BK; kk++) {
            float a[8], b[8];
            #pragma unroll
            for (int i=0;i<8;i++) a[i] = As[kk][ty*8+i];
            #pragma unroll
            for (int j=0;j<8;j++) b[j] = Bs[kk][tx*8+j];
            #pragma unroll
            for (int i=0;i<8;i++)
                #pragma unroll
                for (int j=0;j<8;j++) acc[i][j] += a[i]*b[j];
        }
        __syncthreads();
    }
    int tx = tid & 15, ty = tid >> 4;
    #pragma unroll
    for (int i=0;i<8;i++){
        int m = m0 + ty*8 + i;
        float* rowp = out + (size_t)m*Dn + n0 + tx*8;
        #pragma unroll
        for (int j=0;j<8;j++) rowp[j] = acc[i][j] + bo[n0 + tx*8 + j];
    }
}

// ============================================================
extern "C" void kernel_launch(void* const* d_in, const int* in_sizes, int n_in,
                              void* d_out, int out_size)
{
    const float* query = (const float*)d_in[0];
    const float* key   = (const float*)d_in[1];
    const float* value = (const float*)d_in[2];
    const float* Wq = (const float*)d_in[3];
    const float* bq = (const float*)d_in[4];
    const float* Wk = (const float*)d_in[5];
    const float* bk = (const float*)d_in[6];
    const float* Wv = (const float*)d_in[7];
    const float* bv = (const float*)d_in[8];
    const float* Wo = (const float*)d_in[9];
    const float* bo = (const float*)d_in[10];

    float* out  = (float*)d_out;
    float* attn = out + (size_t)Bn * Sn * Dn;   // second tuple element

    float* gQ;  cudaGetSymbolAddress((void**)&gQ,  g_Q);
    float* gK;  cudaGetSymbolAddress((void**)&gK,  g_K);
    float* gV;  cudaGetSymbolAddress((void**)&gV,  g_V);

    dim3 projGrid(Dn/128, Mn/128);          // (8, 32)
    proj_kernel<<<projGrid, 256>>>(query, Wq, bq, gQ);
    proj_kernel<<<projGrid, 256>>>(key,   Wk, bk, gK);
    proj_kernel<<<projGrid, 256>>>(value, Wv, bv, gV);

    dim3 scoreGrid(Sn/128, Sn/128, BHn);    // (16, 16, 32)
    scores_kernel<<<scoreGrid, 256>>>(attn);

    topk_softmax_kernel<<<BHn * Sn, 256>>>(attn);

    dim3 avGrid(1, Sn/128, BHn);            // (1, 16, 32)
    av_kernel<<<avGrid, 256>>>(attn);

    dim3 outGrid(Dn/128, Mn/128);           // (8, 32)
    outproj_kernel<<<outGrid, 256>>>(Wo, bo, out);
}

// round 4
// speedup vs baseline: 1.1789x; 1.1789x over previous
#include <cuda_runtime.h>
#include <cstdint>

#define Bn 2
#define Sn 2048
#define Dn 1024
#define Hn 16
#define HDn 64
#define BHn (Bn*Hn)
#define Mn (Bn*Sn)       // 4096
#define KSEL 1024        // top-k count

// ---- scratch (static device allocations; no cudaMalloc allowed) ----
__device__ float g_Q[Bn*Hn*Sn*HDn];   // (b,h,s,hd)
__device__ float g_K[Bn*Hn*Sn*HDn];
__device__ float g_V[Bn*Hn*Sn*HDn];
__device__ float g_AV[Bn*Hn*Sn*HDn];

// ============================================================
// Kernel 1: batched projections. blockIdx.z selects (A,W,bias,Out).
// C = A @ W^T + bias, scattered to (b,h,s,hd).
// ============================================================
__global__ __launch_bounds__(256) void proj3_kernel(
    const float* __restrict__ Aq, const float* __restrict__ Ak, const float* __restrict__ Av,
    const float* __restrict__ Wq, const float* __restrict__ Wk, const float* __restrict__ Wv,
    const float* __restrict__ bq, const float* __restrict__ bk, const float* __restrict__ bv,
    float* __restrict__ Oq, float* __restrict__ Ok, float* __restrict__ Ov)
{
    const float* A; const float* W; const float* bias; float* Out;
    if (blockIdx.z == 0)      { A = Aq; W = Wq; bias = bq; Out = Oq; }
    else if (blockIdx.z == 1) { A = Ak; W = Wk; bias = bk; Out = Ok; }
    else                      { A = Av; W = Wv; bias = bv; Out = Ov; }

    const int BK = 16;
    __shared__ float As[BK][128];
    __shared__ float Bs[BK][128];
    int m0 = blockIdx.y * 128;
    int n0 = blockIdx.x * 128;
    int tid = threadIdx.x;
    float acc[8][8];
    #pragma unroll
    for (int i=0;i<8;i++)
        #pragma unroll
        for (int j=0;j<8;j++) acc[i][j]=0.f;

    for (int k0 = 0; k0 < Dn; k0 += BK) {
        #pragma unroll
        for (int i = 0; i < 2; i++) {
            int idx = tid + i*256;
            int r = idx >> 2;
            int c4 = idx & 3;
            float4 v = *(const float4*)(A + (size_t)(m0 + r)*Dn + k0 + c4*4);
            As[c4*4+0][r]=v.x; As[c4*4+1][r]=v.y; As[c4*4+2][r]=v.z; As[c4*4+3][r]=v.w;
        }
        #pragma unroll
        for (int i = 0; i < 2; i++) {
            int idx = tid + i*256;
            int r = idx >> 2;
            int c4 = idx & 3;
            float4 v = *(const float4*)(W + (size_t)(n0 + r)*Dn + k0 + c4*4);
            Bs[c4*4+0][r]=v.x; Bs[c4*4+1][r]=v.y; Bs[c4*4+2][r]=v.z; Bs[c4*4+3][r]=v.w;
        }
        __syncthreads();
        int tx = tid & 15, ty = tid >> 4;
        #pragma unroll
        for (int kk = 0; kk < BK; kk++) {
            float a[8], b[8];
            #pragma unroll
            for (int i=0;i<8;i++) a[i] = As[kk][ty*8+i];
            #pragma unroll
            for (int j=0;j<8;j++) b[j] = Bs[kk][tx*8+j];
            #pragma unroll
            for (int i=0;i<8;i++)
                #pragma unroll
                for (int j=0;j<8;j++) acc[i][j] += a[i]*b[j];
        }
        __syncthreads();
    }
    int tx = tid & 15, ty = tid >> 4;
    #pragma unroll
    for (int i=0;i<8;i++){
        int m = m0 + ty*8 + i;
        int b = m / Sn, s = m % Sn;
        #pragma unroll
        for (int j=0;j<8;j++){
            int n = n0 + tx*8 + j;
            int h = n >> 6, hd = n & 63;
            Out[(((size_t)(b*Hn + h))*Sn + s)*HDn + hd] = acc[i][j] + bias[n];
        }
    }
}

// ============================================================
// Kernel 2: scores[bh][q][k] = scale * dot(Q[bh][q], K[bh][k])
// (proven from R2)
// ============================================================
__global__ __launch_bounds__(256) void scores_kernel(float* __restrict__ attn)
{
    const int BK = 16;
    __shared__ float As[BK][128];
    __shared__ float Bs[BK][128];
    int bh = blockIdx.z;
    int q0 = blockIdx.y * 128;
    int n0 = blockIdx.x * 128;
    const float* Qb = g_Q + (size_t)bh * Sn * HDn;
    const float* Kb = g_K + (size_t)bh * Sn * HDn;
    float* Cb = attn + (size_t)bh * Sn * Sn;
    int tid = threadIdx.x;
    float acc[8][8];
    #pragma unroll
    for (int i=0;i<8;i++)
        #pragma unroll
        for (int j=0;j<8;j++) acc[i][j]=0.f;

    for (int k0 = 0; k0 < HDn; k0 += BK) {
        #pragma unroll
        for (int i = 0; i < 2; i++) {
            int idx = tid + i*256;
            int r = idx >> 2;
            int c4 = idx & 3;
            float4 v = *(const float4*)(Qb + (size_t)(q0 + r)*HDn + k0 + c4*4);
            As[c4*4+0][r]=v.x; As[c4*4+1][r]=v.y; As[c4*4+2][r]=v.z; As[c4*4+3][r]=v.w;
        }
        #pragma unroll
        for (int i = 0; i < 2; i++) {
            int idx = tid + i*256;
            int r = idx >> 2;
            int c4 = idx & 3;
            float4 v = *(const float4*)(Kb + (size_t)(n0 + r)*HDn + k0 + c4*4);
            Bs[c4*4+0][r]=v.x; Bs[c4*4+1][r]=v.y; Bs[c4*4+2][r]=v.z; Bs[c4*4+3][r]=v.w;
        }
        __syncthreads();
        int tx = tid & 15, ty = tid >> 4;
        #pragma unroll
        for (int kk = 0; kk < BK; kk++) {
            float a[8], b[8];
            #pragma unroll
            for (int i=0;i<8;i++) a[i] = As[kk][ty*8+i];
            #pragma unroll
            for (int j=0;j<8;j++) b[j] = Bs[kk][tx*8+j];
            #pragma unroll
            for (int i=0;i<8;i++)
                #pragma unroll
                for (int j=0;j<8;j++) acc[i][j] += a[i]*b[j];
        }
        __syncthreads();
    }
    const float scale = 0.125f;   // HD^-0.5
    int tx = tid & 15, ty = tid >> 4;
    #pragma unroll
    for (int i=0;i<8;i++){
        int q = q0 + ty*8 + i;
        float* rowp = Cb + (size_t)q * Sn + n0 + tx*8;
        float4 v0 = make_float4(acc[i][0]*scale, acc[i][1]*scale, acc[i][2]*scale, acc[i][3]*scale);
        float4 v1 = make_float4(acc[i][4]*scale, acc[i][5]*scale, acc[i][6]*scale, acc[i][7]*scale);
        *(float4*)(rowp)     = v0;
        *(float4*)(rowp + 4) = v1;
    }
}

// ============================================================
// Kernel 3: per-WARP exact top-k (4-pass 256-bin radix select) + softmax.
// One row (2048 floats) per warp, held in registers (64/lane).
// Only __syncwarp — no block barriers. In-place on attn.
// ============================================================
__global__ __launch_bounds__(256) void topk_softmax_kernel(float* __restrict__ attn)
{
    __shared__ int hist[8][256];

    const int tid  = threadIdx.x;
    const int lane = tid & 31;
    const int w    = tid >> 5;
    const size_t row = (size_t)blockIdx.x * 8 + w;
    float* rowp = attn + row * (size_t)Sn;
    int* wh = hist[w];

    // load row: 16 float4 per lane, strided
    float x[64];
    #pragma unroll
    for (int j = 0; j < 16; j++) {
        float4 v = *(const float4*)(rowp + lane*4 + j*128);
        x[j*4+0]=v.x; x[j*4+1]=v.y; x[j*4+2]=v.z; x[j*4+3]=v.w;
    }

    // row max
    float lmax = -3.4e38f;
    #pragma unroll
    for (int e = 0; e < 64; e++) lmax = fmaxf(lmax, x[e]);
    #pragma unroll
    for (int o=16;o>0;o>>=1) lmax = fmaxf(lmax, __shfl_xor_sync(0xffffffffu, lmax, o));
    float gmax = lmax;

    // 4-pass MSB-first radix select on order-preserving uint keys
    unsigned prefix = 0u;
    int r = KSEL;
    #pragma unroll 1
    for (int pass = 3; pass >= 0; pass--) {
        int shift = pass * 8;
        unsigned pmask = (pass == 3) ? 0u : (0xFFFFFFFFu << (shift + 8));
        #pragma unroll
        for (int i = 0; i < 8; i++) wh[lane + i*32] = 0;
        __syncwarp();
        #pragma unroll
        for (int e = 0; e < 64; e++) {
            unsigned uf = __float_as_uint(x[e]);
            unsigned u  = (uf & 0x80000000u) ? ~uf : (uf | 0x80000000u);
            if ((u & pmask) == prefix)
                atomicAdd(&wh[(u >> shift) & 255u], 1);
        }
        __syncwarp();
        int h[8]; int lsum = 0;
        #pragma unroll
        for (int i=0;i<8;i++){ h[i] = wh[lane*8+i]; lsum += h[i]; }
        int incl = lsum;
        #pragma unroll
        for (int o=1;o<32;o<<=1){
            int t2 = __shfl_up_sync(0xffffffffu, incl, o);
            if (lane >= o) incl += t2;
        }
        int total = __shfl_sync(0xffffffffu, incl, 31);
        int A = total - incl;                 // keys in bins above lane's 8 bins
        int s[9]; s[8] = 0;
        #pragma unroll
        for (int i=7;i>=0;i--) s[i] = s[i+1] + h[i];
        int found = -1, rnew = 0;
        #pragma unroll
        for (int i=0;i<8;i++){
            int ge  = A + s[i];               // count(byte >= bin)
            int gen = A + s[i+1];             // count(byte >= bin+1)
            if (ge >= r && gen < r){ found = i; rnew = r - gen; }
        }
        unsigned ball = __ballot_sync(0xffffffffu, found >= 0);
        int src = __ffs(ball) - 1;
        unsigned bsel = __shfl_sync(0xffffffffu,
                                    (found >= 0) ? (unsigned)(lane*8 + found) : 0u, src);
        r = __shfl_sync(0xffffffffu, rnew, src);
        prefix |= (bsel << shift);
        __syncwarp();
    }
    unsigned thr = prefix;   // exact k-th largest key (ties all kept, == reference)

    // masked exp + sum + normalized write
    float lsumf = 0.f;
    #pragma unroll
    for (int e = 0; e < 64; e++) {
        unsigned uf = __float_as_uint(x[e]);
        unsigned u  = (uf & 0x80000000u) ? ~uf : (uf | 0x80000000u);
        x[e] = (u >= thr) ? __expf(x[e] - gmax) : 0.f;
        lsumf += x[e];
    }
    #pragma unroll
    for (int o=16;o>0;o>>=1) lsumf += __shfl_xor_sync(0xffffffffu, lsumf, o);
    float inv = 1.f / lsumf;
    #pragma unroll
    for (int j = 0; j < 16; j++) {
        float4 v = make_float4(x[j*4+0]*inv, x[j*4+1]*inv, x[j*4+2]*inv, x[j*4+3]*inv);
        *(float4*)(rowp + lane*4 + j*128) = v;
    }
}

// ============================================================
// Kernel 4: AV[bh][q][d] = sum_k attn[bh][q][k] * V[bh][k][d]
// 256x64 tile, 8x8 per thread, As padded stride 257 (conflict-free).
// ============================================================
#define AS_STRIDE 257
__global__ __launch_bounds__(256) void av_kernel(const float* __restrict__ attn)
{
    const int BK = 32;
    __shared__ float As[BK*AS_STRIDE];   // [k][m], m stride 257
    __shared__ float Bs[BK][64];         // [k][n]
    int bh = blockIdx.y;
    int m0 = blockIdx.x * 256;
    const float* Arow = attn + (size_t)bh * Sn * Sn;
    const float* Vb   = g_V  + (size_t)bh * Sn * HDn;
    float*       Cb   = g_AV + (size_t)bh * Sn * HDn;
    int tid = threadIdx.x;
    int tx = tid & 7;        // 8 cols of 8
    int ty = tid >> 3;       // 32 rows of 8
    float acc[8][8];
    #pragma unroll
    for (int i=0;i<8;i++)
        #pragma unroll
        for (int j=0;j<8;j++) acc[i][j]=0.f;

    for (int k0 = 0; k0 < Sn; k0 += BK) {
        // A: 256 rows x 32 k = 2048 float4, 8 per thread
        #pragma unroll
        for (int i = 0; i < 8; i++) {
            int idx = tid + i*256;      // 0..2047
            int r  = idx >> 3;          // 0..255 (m)
            int c4 = idx & 7;           // 0..7  (k group)
            float4 v = *(const float4*)(Arow + (size_t)(m0 + r)*Sn + k0 + c4*4);
            As[(c4*4+0)*AS_STRIDE + r]=v.x;
            As[(c4*4+1)*AS_STRIDE + r]=v.y;
            As[(c4*4+2)*AS_STRIDE + r]=v.z;
            As[(c4*4+3)*AS_STRIDE + r]=v.w;
        }
        // B: 32 rows x 64 d = 512 float4, 2 per thread
        #pragma unroll
        for (int i = 0; i < 2; i++) {
            int idx = tid + i*256;
            int r = idx >> 4;           // 0..31 (k)
            int c4 = idx & 15;          // 0..15
            float4 v = *(const float4*)(Vb + (size_t)(k0 + r)*HDn + c4*4);
            *(float4*)&Bs[r][c4*4] = v;
        }
        __syncthreads();
        #pragma unroll
        for (int kk = 0; kk < BK; kk++) {
            float a[8], b[8];
            #pragma unroll
            for (int i=0;i<8;i++) a[i] = As[kk*AS_STRIDE + ty*8 + i];
            #pragma unroll
            for (int j=0;j<8;j++) b[j] = Bs[kk][tx*8+j];
            #pragma unroll
            for (int i=0;i<8;i++)
                #pragma unroll
                for (int j=0;j<8;j++) acc[i][j] += a[i]*b[j];
        }
        __syncthreads();
    }
    #pragma unroll
    for (int i=0;i<8;i++){
        int m = m0 + ty*8 + i;
        float4 v0 = make_float4(acc[i][0], acc[i][1], acc[i][2], acc[i][3]);
        float4 v1 = make_float4(acc[i][4], acc[i][5], acc[i][6], acc[i][7]);
        *(float4*)&Cb[(size_t)m*HDn + tx*8]     = v0;
        *(float4*)&Cb[(size_t)m*HDn + tx*8 + 4] = v1;
    }
}

// ============================================================
// Kernel 5: out[m][n] = sum_k AVview[m][k] * Wo[n][k] + bo[n]
// ============================================================
__global__ __launch_bounds__(256) void outproj_kernel(
    const float* __restrict__ Wo, const float* __restrict__ bo,
    float* __restrict__ out)
{
    const int BK = 16;
    __shared__ float As[BK][128];
    __shared__ float Bs[BK][128];
    int m0 = blockIdx.y * 128;
    int n0 = blockIdx.x * 128;
    int tid = threadIdx.x;
    float acc[8][8];
    #pragma unroll
    for (int i=0;i<8;i++)
        #pragma unroll
        for (int j=0;j<8;j++) acc[i][j]=0.f;

    for (int k0 = 0; k0 < Dn; k0 += BK) {
        int h   = k0 >> 6;
        int hd0 = k0 & 63;
        #pragma unroll
        for (int i = 0; i < 2; i++) {
            int idx = tid + i*256;
            int r = idx >> 2;
            int c4 = idx & 3;
            int m = m0 + r;
            int b = m / Sn, s = m % Sn;
            float4 v = *(const float4*)(g_AV + (((size_t)(b*Hn + h))*Sn + s)*HDn + hd0 + c4*4);
            As[c4*4+0][r]=v.x; As[c4*4+1][r]=v.y; As[c4*4+2][r]=v.z; As[c4*4+3][r]=v.w;
        }
        #pragma unroll
        for (int i = 0; i < 2; i++) {
            int idx = tid + i*256;
            int r = idx >> 2;
            int c4 = idx & 3;
            float4 v = *(const float4*)(Wo + (size_t)(n0 + r)*Dn + k0 + c4*4);
            Bs[c4*4+0][r]=v.x; Bs[c4*4+1][r]=v.y; Bs[c4*4+2][r]=v.z; Bs[c4*4+3][r]=v.w;
        }
        __syncthreads();
        int tx = tid & 15, ty = tid >> 4;
        #pragma unroll
        for (int kk = 0; kk < BK; kk++) {
            float a[8], b[8];
            #pragma unroll
            for (int i=0;i<8;i++) a[i] = As[kk][ty*8+i];
            #pragma unroll
            for (int j=0;j<8;j++) b[j] = Bs[kk][tx*8+j];
            #pragma unroll
            for (int i=0;i<8;i++)
                #pragma unroll
                for (int j=0;j<8;j++) acc[i][j] += a[i]*b[j];
        }
        __syncthreads();
    }
    int tx = tid & 15, ty = tid >> 4;
    #pragma unroll
    for (int i=0;i<8;i++){
        int m = m0 + ty*8 + i;
        float* rowp = out + (size_t)m*Dn + n0 + tx*8;
        #pragma unroll
        for (int j=0;j<8;j++) rowp[j] = acc[i][j] + bo[n0 + tx*8 + j];
    }
}

// ============================================================
extern "C" void kernel_launch(void* const* d_in, const int* in_sizes, int n_in,
                              void* d_out, int out_size)
{
    const float* query = (const float*)d_in[0];
    const float* key   = (const float*)d_in[1];
    const float* value = (const float*)d_in[2];
    const float* Wq = (const float*)d_in[3];
    const float* bq = (const float*)d_in[4];
    const float* Wk = (const float*)d_in[5];
    const float* bk = (const float*)d_in[6];
    const float* Wv = (const float*)d_in[7];
    const float* bv = (const float*)d_in[8];
    const float* Wo = (const float*)d_in[9];
    const float* bo = (const float*)d_in[10];

    float* out  = (float*)d_out;
    float* attn = out + (size_t)Bn * Sn * Dn;   // second tuple element

    float* gQ;  cudaGetSymbolAddress((void**)&gQ,  g_Q);
    float* gK;  cudaGetSymbolAddress((void**)&gK,  g_K);
    float* gV;  cudaGetSymbolAddress((void**)&gV,  g_V);

    dim3 projGrid(Dn/128, Mn/128, 3);       // (8, 32, 3)
    proj3_kernel<<<projGrid, 256>>>(query, key, value,
                                    Wq, Wk, Wv, bq, bk, bv,
                                    gQ, gK, gV);

    dim3 scoreGrid(Sn/128, Sn/128, BHn);    // (16, 16, 32)
    scores_kernel<<<scoreGrid, 256>>>(attn);

    topk_softmax_kernel<<<BHn * Sn / 8, 256>>>(attn);   // 8192 blocks, 1 row/warp

    dim3 avGrid(Sn/256, BHn);               // (8, 32)
    av_kernel<<<avGrid, 256>>>(attn);

    dim3 outGrid(Dn/128, Mn/128);           // (8, 32)
    outproj_kernel<<<outGrid, 256>>>(Wo, bo, out);
}